// round 1
// baseline (speedup 1.0000x reference)
#include <cuda_runtime.h>

// Problem dims
#define BB 4096
#define DD 256
#define UU 512

// Scratch for the two projection GEMMs (device globals: allocation-free rule)
static __device__ float g_xp[(size_t)BB * 5 * UU];   // 4096 x 2560
static __device__ float g_rp[(size_t)BB * 3 * UU];   // 4096 x 1536

// ---------------- packed fp32x2 helpers (sm_100+) ----------------
__device__ __forceinline__ unsigned long long pack_dup(float a) {
    unsigned long long d;
    asm("mov.b64 %0, {%1, %1};" : "=l"(d) : "f"(a));
    return d;
}
__device__ __forceinline__ void ffma2(unsigned long long& acc,
                                      unsigned long long a,
                                      unsigned long long b) {
    // two independent fp32 FMAs per instruction; rounding identical to fmaf
    asm("fma.rn.f32x2 %0, %1, %2, %0;" : "+l"(acc) : "l"(a), "l"(b));
}

// ---------------- 128x128x8 fp32 GEMM, 8x8 per thread (4 f32x2 pairs) -------
// C = A(MxK) * B(KxN), all row-major. M=4096 fixed by grid. K,N divisible by 8/128.
template<int SEL, int K, int N>
__global__ __launch_bounds__(256, 2)
void sgemm128(const float* __restrict__ A, const float* __restrict__ Bm) {
    float* __restrict__ C = (SEL == 0) ? g_xp : g_rp;

    __shared__ float As[8][128];   // transposed A tile: As[k][m]
    __shared__ float Bs[8][128];   // Bs[k][n]

    const int tid = threadIdx.x;
    const int bm  = blockIdx.y;
    const int bn  = blockIdx.x;

    // global-load mapping
    const int aRow = tid >> 1;          // 0..127
    const int aCol = (tid & 1) << 2;    // 0 or 4
    const int bRow = tid >> 5;          // 0..7
    const int bCol = (tid & 31) << 2;   // 0..124

    const float* Aptr = A + (size_t)(bm * 128 + aRow) * K + aCol;
    const float* Bptr = Bm + (size_t)bRow * N + bn * 128 + bCol;

    // compute mapping: 16x16 thread grid, each does 8 rows x 8 cols
    const int tx = tid & 15;
    const int ty = tid >> 4;

    unsigned long long acc[8][4];       // 8 rows x 4 col-pairs (fp32x2)
    #pragma unroll
    for (int i = 0; i < 8; i++)
        #pragma unroll
        for (int j = 0; j < 4; j++) acc[i][j] = 0ull;

    // prefetch first tile
    float4 aReg = *(const float4*)Aptr;
    float4 bReg = *(const float4*)Bptr;

    const int nIter = K / 8;
    for (int it = 0; it < nIter; ++it) {
        As[aCol + 0][aRow] = aReg.x;
        As[aCol + 1][aRow] = aReg.y;
        As[aCol + 2][aRow] = aReg.z;
        As[aCol + 3][aRow] = aReg.w;
        *(float4*)(&Bs[bRow][bCol]) = bReg;
        __syncthreads();

        if (it + 1 < nIter) {           // prefetch next tile behind compute
            Aptr += 8;
            Bptr += (size_t)8 * N;
            aReg = *(const float4*)Aptr;
            bReg = *(const float4*)Bptr;
        }

        #pragma unroll
        for (int k = 0; k < 8; k++) {
            float4 a0 = *(const float4*)(&As[k][ty * 8]);
            float4 a1 = *(const float4*)(&As[k][ty * 8 + 4]);
            const unsigned long long* bsk =
                (const unsigned long long*)(&Bs[k][tx * 8]);
            unsigned long long b0 = bsk[0];
            unsigned long long b1 = bsk[1];
            unsigned long long b2 = bsk[2];
            unsigned long long b3 = bsk[3];
            float a[8] = {a0.x, a0.y, a0.z, a0.w, a1.x, a1.y, a1.z, a1.w};
            #pragma unroll
            for (int i = 0; i < 8; i++) {
                unsigned long long ad = pack_dup(a[i]);
                ffma2(acc[i][0], ad, b0);
                ffma2(acc[i][1], ad, b1);
                ffma2(acc[i][2], ad, b2);
                ffma2(acc[i][3], ad, b3);
            }
        }
        __syncthreads();
    }

    // epilogue: unpack and store
    float* Crow = C + (size_t)(bm * 128 + ty * 8) * N + bn * 128 + tx * 8;
    #pragma unroll
    for (int i = 0; i < 8; i++) {
        float v[8];
        #pragma unroll
        for (int j = 0; j < 4; j++) {
            asm("mov.b64 {%0, %1}, %2;"
                : "=f"(v[2 * j]), "=f"(v[2 * j + 1]) : "l"(acc[i][j]));
        }
        *(float4*)(Crow + (size_t)i * N)     = make_float4(v[0], v[1], v[2], v[3]);
        *(float4*)(Crow + (size_t)i * N + 4) = make_float4(v[4], v[5], v[6], v[7]);
    }
}

// ---------------- fused elementwise LSTM epilogue ----------------
__device__ __forceinline__ float sigf(float x) {
    return 1.0f / (1.0f + __expf(-x));
}

struct F4v { float v[4]; };
__device__ __forceinline__ F4v ld4(const float* p) {
    float4 t = *(const float4*)p;
    F4v r; r.v[0] = t.x; r.v[1] = t.y; r.v[2] = t.z; r.v[3] = t.w;
    return r;
}

__global__ __launch_bounds__(256)
void eltwise(const float* __restrict__ t, const float* __restrict__ c0,
             const float* __restrict__ ktime, float* __restrict__ out) {
    int idx = blockIdx.x * 256 + threadIdx.x;   // over B*U/4
    int b = idx >> 7;                           // U/4 = 128 vec4 groups per row
    int u = (idx & 127) << 2;

    const float tb = __ldg(&t[b]);
    const float* xp = g_xp + (size_t)b * (5 * UU) + u;
    const float* rp = g_rp + (size_t)b * (3 * UU) + u;

    F4v xi  = ld4(xp + 0 * UU);
    F4v xc  = ld4(xp + 1 * UU);
    F4v xo  = ld4(xp + 2 * UU);
    F4v xt1 = ld4(xp + 3 * UU);
    F4v xt2 = ld4(xp + 4 * UU);
    F4v ri  = ld4(rp + 0 * UU);
    F4v rc  = ld4(rp + 1 * UU);
    F4v ro  = ld4(rp + 2 * UU);
    F4v c0v = ld4(c0 + (size_t)b * UU + u);
    F4v k1  = ld4(ktime + 0 * UU + u);
    F4v k2  = ld4(ktime + 1 * UU + u);
    F4v ko  = ld4(ktime + 2 * UU + u);

    float hv[4], cmv[4];
    #pragma unroll
    for (int j = 0; j < 4; j++) {
        float i_g = sigf(xi.v[j] + ri.v[j]);
        float t1  = sigf(xt1.v[j] + sigf(tb * k1.v[j]));
        float t1c = (t1 > -1e-5f) ? -1e-5f : t1;   // faithful to reference where()
        float t2  = sigf(xt2.v[j] + sigf(tb * k2.v[j]));
        float ct  = tanhf(xc.v[j] + rc.v[j]);
        float cm_ = (1.0f - i_g * t1) * c0v.v[j] + i_g * ct * t1c;
        float cm  = (1.0f - i_g) * c0v.v[j] + i_g * ct * t2;
        float o   = sigf(xo.v[j] + ro.v[j] + tb * ko.v[j]);
        hv[j]  = tanhf(cm_) * o;
        cmv[j] = cm;
    }

    float* hout = out + (size_t)b * UU + u;
    float* cout = out + (size_t)BB * UU + (size_t)b * UU + u;
    *(float4*)hout = make_float4(hv[0], hv[1], hv[2], hv[3]);
    *(float4*)cout = make_float4(cmv[0], cmv[1], cmv[2], cmv[3]);
}

// ---------------- launch ----------------
extern "C" void kernel_launch(void* const* d_in, const int* in_sizes, int n_in,
                              void* d_out, int out_size) {
    const float* x     = (const float*)d_in[0];
    const float* t     = (const float*)d_in[1];
    const float* h0    = (const float*)d_in[2];
    const float* c0    = (const float*)d_in[3];
    const float* kern  = (const float*)d_in[4];
    const float* rkern = (const float*)d_in[5];
    const float* ktime = (const float*)d_in[6];
    float* out = (float*)d_out;

    dim3 g1(5 * UU / 128, BB / 128);   // (20, 32): x @ kernel -> g_xp
    sgemm128<0, DD, 5 * UU><<<g1, 256>>>(x, kern);

    dim3 g2(3 * UU / 128, BB / 128);   // (12, 32): h0 @ recurrent_kernel -> g_rp
    sgemm128<1, UU, 3 * UU><<<g2, 256>>>(h0, rkern);

    eltwise<<<(BB * UU / 4) / 256, 256>>>(t, c0, ktime, out);
}

// round 5
// speedup vs baseline: 1.7774x; 1.7774x over previous
#include <cuda_runtime.h>
#include <cuda_bf16.h>
#include <cstdint>

#define BB 4096
#define DD 256
#define UU 512

typedef __nv_bfloat16 bf16;

// ---------------- scratch (device globals: allocation-free rule) -------------
static __device__ float g_xp[(size_t)BB * 5 * UU];            // 4096 x 2560 f32
static __device__ float g_rp[(size_t)BB * 3 * UU];            // 4096 x 1536 f32

static __device__ bf16 g_xhi[(size_t)BB * DD];
static __device__ bf16 g_xlo[(size_t)BB * DD];
static __device__ bf16 g_hhi[(size_t)BB * UU];
static __device__ bf16 g_hlo[(size_t)BB * UU];
static __device__ bf16 g_whi[(size_t)DD * 5 * UU];            // [256][2560] K-major
static __device__ bf16 g_wlo[(size_t)DD * 5 * UU];
static __device__ bf16 g_rhi[(size_t)UU * 3 * UU];            // [512][1536]
static __device__ bf16 g_rlo[(size_t)UU * 3 * UU];

// ---------------- PTX helpers ----------------
__device__ __forceinline__ uint32_t smem_u32(const void* p) {
    uint32_t a;
    asm("{ .reg .u64 t; cvta.to.shared.u64 t, %1; cvt.u32.u64 %0, t; }"
        : "=r"(a) : "l"(p));
    return a;
}
__device__ __forceinline__ void cp16(uint32_t saddr, const void* gaddr) {
    asm volatile("cp.async.cg.shared.global [%0], [%1], 16;"
                 :: "r"(saddr), "l"(gaddr) : "memory");
}
#define CP_COMMIT() asm volatile("cp.async.commit_group;" ::: "memory")
#define CP_WAIT(n)  asm volatile("cp.async.wait_group %0;" :: "n"(n) : "memory")

__device__ __forceinline__ void ldm_x4(uint32_t* r, uint32_t addr) {
    asm volatile("ldmatrix.sync.aligned.m8n8.x4.shared.b16 {%0,%1,%2,%3}, [%4];"
                 : "=r"(r[0]), "=r"(r[1]), "=r"(r[2]), "=r"(r[3]) : "r"(addr));
}
__device__ __forceinline__ void ldm_x4t(uint32_t* r, uint32_t addr) {
    asm volatile("ldmatrix.sync.aligned.m8n8.x4.trans.shared.b16 {%0,%1,%2,%3}, [%4];"
                 : "=r"(r[0]), "=r"(r[1]), "=r"(r[2]), "=r"(r[3]) : "r"(addr));
}
__device__ __forceinline__ void mma_bf16(float* d, const uint32_t* a, const uint32_t* b) {
    asm volatile("mma.sync.aligned.m16n8k16.row.col.f32.bf16.bf16.f32 "
                 "{%0,%1,%2,%3}, {%4,%5,%6,%7}, {%8,%9}, {%0,%1,%2,%3};"
                 : "+f"(d[0]), "+f"(d[1]), "+f"(d[2]), "+f"(d[3])
                 : "r"(a[0]), "r"(a[1]), "r"(a[2]), "r"(a[3]), "r"(b[0]), "r"(b[1]));
}

// ---------------- conversion: fp32 -> bf16 hi/lo ----------------
__global__ void split_rows(const float* __restrict__ src,
                           bf16* __restrict__ hi, bf16* __restrict__ lo, int n) {
    int i = blockIdx.x * 256 + threadIdx.x;
    if (i < n) {
        float v = src[i];
        bf16 h = __float2bfloat16(v);
        hi[i] = h;
        lo[i] = __float2bfloat16(v - __bfloat162float(h));
    }
}

// ---------------- HMMA GEMM: C[4096][NTOT] = A[4096][K] * B[K][NTOT] ---------
// hi/lo split folded into 3 K-phases: Ah*Bh, Ah*Bl, Al*Bh (fp32 accum).
// 128x128x32 tiles, 8 warps (2x4), 64x32 per warp, cp.async double buffer.
#define APAD 8
#define BPAD 8
template<int K, int NTOT, int SEL>
__global__ __launch_bounds__(256)
void hmma_gemm(const bf16* __restrict__ Ahi, const bf16* __restrict__ Alo,
               const bf16* __restrict__ Bhi, const bf16* __restrict__ Blo) {
    float* __restrict__ C = (SEL == 0) ? g_xp : g_rp;

    __shared__ __align__(16) bf16 As[2][128][32 + APAD];   // [buf][m][k]
    __shared__ __align__(16) bf16 Bs[2][32][128 + BPAD];   // [buf][k][n]

    const int tid = threadIdx.x;
    const int wid = tid >> 5, lane = tid & 31;
    const int bm = blockIdx.y, bn = blockIdx.x;
    const int wm = wid >> 2, wn = wid & 3;                 // 2 x 4 warp grid

    // global-load mapping
    const int aRow = tid >> 2;          // 0..63 (+64)
    const int aSeg = tid & 3;           // 16B seg along k (4 segs x 8 bf16 = 32)
    const int bRow = tid >> 4;          // 0..15 (+16)
    const int bSeg = tid & 15;          // 16B seg along n (16 segs x 8 bf16 = 128)

    constexpr int KCH = K / 32;
    constexpr int NC  = 3 * KCH;

    const uint32_t sA0 = smem_u32(&As[0][0][0]);
    const uint32_t sB0 = smem_u32(&Bs[0][0][0]);
    constexpr uint32_t A_BUF = 128 * (32 + APAD) * 2;      // bytes per A buffer
    constexpr uint32_t B_BUF = 32 * (128 + BPAD) * 2;
    constexpr uint32_t A_ROW = (32 + APAD) * 2;            // 80 B
    constexpr uint32_t B_ROW = (128 + BPAD) * 2;           // 272 B

    auto load_chunk = [&](int kc, int buf) {
        const int p  = kc / KCH;
        const int kk = kc - p * KCH;
        const bf16* Asrc = (p == 2) ? Alo : Ahi;
        const bf16* Bsrc = (p == 1) ? Blo : Bhi;
        const bf16* ag = Asrc + (size_t)(bm * 128 + aRow) * K + kk * 32 + aSeg * 8;
        uint32_t sa = sA0 + buf * A_BUF + aRow * A_ROW + aSeg * 16;
        cp16(sa, ag);
        cp16(sa + 64 * A_ROW, ag + (size_t)64 * K);
        const bf16* bg = Bsrc + (size_t)(kk * 32 + bRow) * NTOT + bn * 128 + bSeg * 8;
        uint32_t sb = sB0 + buf * B_BUF + bRow * B_ROW + bSeg * 16;
        cp16(sb, bg);
        cp16(sb + 16 * B_ROW, bg + (size_t)16 * NTOT);
        CP_COMMIT();
    };

    float acc[4][4][4];
    #pragma unroll
    for (int i = 0; i < 4; i++)
        #pragma unroll
        for (int j = 0; j < 4; j++)
            #pragma unroll
            for (int v = 0; v < 4; v++) acc[i][j][v] = 0.0f;

    load_chunk(0, 0);

    // ldmatrix base offsets (per lane)
    const int lrow = lane & 15;          // matrix row within 16
    const int lhalf = lane >> 4;         // 0/1: second-8 column group

    for (int kc = 0; kc < NC; ++kc) {
        if (kc + 1 < NC) { load_chunk(kc + 1, (kc + 1) & 1); CP_WAIT(1); }
        else             { CP_WAIT(0); }
        __syncthreads();

        const int buf = kc & 1;
        const uint32_t aBase = sA0 + buf * A_BUF;
        const uint32_t bBase = sB0 + buf * B_BUF;

        #pragma unroll
        for (int ks = 0; ks < 32; ks += 16) {
            uint32_t afr[4][4];
            #pragma unroll
            for (int mf = 0; mf < 4; mf++) {
                uint32_t addr = aBase + (wm * 64 + mf * 16 + lrow) * A_ROW
                              + (ks + lhalf * 8) * 2;
                ldm_x4(afr[mf], addr);
            }
            uint32_t bfr[4][2];
            #pragma unroll
            for (int nh = 0; nh < 2; nh++) {
                uint32_t addr = bBase + (ks + lrow) * B_ROW
                              + (wn * 32 + nh * 16 + lhalf * 8) * 2;
                uint32_t r[4];
                ldm_x4t(r, addr);
                bfr[2 * nh][0] = r[0]; bfr[2 * nh][1] = r[1];
                bfr[2 * nh + 1][0] = r[2]; bfr[2 * nh + 1][1] = r[3];
            }
            #pragma unroll
            for (int mf = 0; mf < 4; mf++)
                #pragma unroll
                for (int nf = 0; nf < 4; nf++)
                    mma_bf16(acc[mf][nf], afr[mf], bfr[nf]);
        }
        __syncthreads();
    }

    // epilogue: d-frag layout m16n8 -> rows (g, g+8), cols q*2, q*2+1
    const int g = lane >> 2, q = lane & 3;
    #pragma unroll
    for (int mf = 0; mf < 4; mf++) {
        const int row0 = bm * 128 + wm * 64 + mf * 16 + g;
        #pragma unroll
        for (int nf = 0; nf < 4; nf++) {
            const int col = bn * 128 + wn * 32 + nf * 8 + q * 2;
            float2 v0 = make_float2(acc[mf][nf][0], acc[mf][nf][1]);
            float2 v1 = make_float2(acc[mf][nf][2], acc[mf][nf][3]);
            *(float2*)(C + (size_t)row0 * NTOT + col)       = v0;
            *(float2*)(C + (size_t)(row0 + 8) * NTOT + col) = v1;
        }
    }
}

// ---------------- fused elementwise LSTM epilogue ----------------
__device__ __forceinline__ float sigf(float x) { return 1.0f / (1.0f + __expf(-x)); }

struct F4v { float v[4]; };
__device__ __forceinline__ F4v ld4(const float* p) {
    float4 t = *(const float4*)p;
    F4v r; r.v[0] = t.x; r.v[1] = t.y; r.v[2] = t.z; r.v[3] = t.w;
    return r;
}

__global__ __launch_bounds__(256)
void eltwise(const float* __restrict__ t, const float* __restrict__ c0,
             const float* __restrict__ ktime, float* __restrict__ out) {
    int idx = blockIdx.x * 256 + threadIdx.x;
    int b = idx >> 7;
    int u = (idx & 127) << 2;

    const float tb = __ldg(&t[b]);
    const float* xp = g_xp + (size_t)b * (5 * UU) + u;
    const float* rp = g_rp + (size_t)b * (3 * UU) + u;

    F4v xi  = ld4(xp + 0 * UU);
    F4v xc  = ld4(xp + 1 * UU);
    F4v xo  = ld4(xp + 2 * UU);
    F4v xt1 = ld4(xp + 3 * UU);
    F4v xt2 = ld4(xp + 4 * UU);
    F4v ri  = ld4(rp + 0 * UU);
    F4v rc  = ld4(rp + 1 * UU);
    F4v ro  = ld4(rp + 2 * UU);
    F4v c0v = ld4(c0 + (size_t)b * UU + u);
    F4v k1  = ld4(ktime + 0 * UU + u);
    F4v k2  = ld4(ktime + 1 * UU + u);
    F4v ko  = ld4(ktime + 2 * UU + u);

    float hv[4], cmv[4];
    #pragma unroll
    for (int j = 0; j < 4; j++) {
        float i_g = sigf(xi.v[j] + ri.v[j]);
        float t1  = sigf(xt1.v[j] + sigf(tb * k1.v[j]));
        float t1c = (t1 > -1e-5f) ? -1e-5f : t1;
        float t2  = sigf(xt2.v[j] + sigf(tb * k2.v[j]));
        float ct  = tanhf(xc.v[j] + rc.v[j]);
        float cm_ = (1.0f - i_g * t1) * c0v.v[j] + i_g * ct * t1c;
        float cm  = (1.0f - i_g) * c0v.v[j] + i_g * ct * t2;
        float o   = sigf(xo.v[j] + ro.v[j] + tb * ko.v[j]);
        hv[j]  = tanhf(cm_) * o;
        cmv[j] = cm;
    }

    float* hout = out + (size_t)b * UU + u;
    float* cout = out + (size_t)BB * UU + (size_t)b * UU + u;
    *(float4*)hout = make_float4(hv[0], hv[1], hv[2], hv[3]);
    *(float4*)cout = make_float4(cmv[0], cmv[1], cmv[2], cmv[3]);
}

// ---------------- launch ----------------
extern "C" void kernel_launch(void* const* d_in, const int* in_sizes, int n_in,
                              void* d_out, int out_size) {
    const float* x     = (const float*)d_in[0];
    const float* t     = (const float*)d_in[1];
    const float* h0    = (const float*)d_in[2];
    const float* c0    = (const float*)d_in[3];
    const float* kern  = (const float*)d_in[4];
    const float* rkern = (const float*)d_in[5];
    const float* ktime = (const float*)d_in[6];
    float* out = (float*)d_out;

    bf16 *xhi, *xlo, *hhi, *hlo, *whi, *wlo, *rhi, *rlo;
    cudaGetSymbolAddress((void**)&xhi, g_xhi);
    cudaGetSymbolAddress((void**)&xlo, g_xlo);
    cudaGetSymbolAddress((void**)&hhi, g_hhi);
    cudaGetSymbolAddress((void**)&hlo, g_hlo);
    cudaGetSymbolAddress((void**)&whi, g_whi);
    cudaGetSymbolAddress((void**)&wlo, g_wlo);
    cudaGetSymbolAddress((void**)&rhi, g_rhi);
    cudaGetSymbolAddress((void**)&rlo, g_rlo);

    split_rows<<<(BB * DD + 255) / 256, 256>>>(x, xhi, xlo, BB * DD);
    split_rows<<<(BB * UU + 255) / 256, 256>>>(h0, hhi, hlo, BB * UU);
    split_rows<<<(DD * 5 * UU + 255) / 256, 256>>>(kern, whi, wlo, DD * 5 * UU);
    split_rows<<<(UU * 3 * UU + 255) / 256, 256>>>(rkern, rhi, rlo, UU * 3 * UU);

    dim3 g1(5 * UU / 128, BB / 128);   // (20, 32)
    hmma_gemm<DD, 5 * UU, 0><<<g1, 256>>>(xhi, xlo, whi, wlo);

    dim3 g2(3 * UU / 128, BB / 128);   // (12, 32)
    hmma_gemm<UU, 3 * UU, 1><<<g2, 256>>>(hhi, hlo, rhi, rlo);

    eltwise<<<(BB * UU / 4) / 256, 256>>>(t, c0, ktime, out);
}

// round 6
// speedup vs baseline: 2.1102x; 1.1873x over previous
#include <cuda_runtime.h>
#include <cuda_bf16.h>
#include <cstdint>

#define BB 4096
#define DD 256
#define UU 512

typedef __nv_bfloat16 bf16;

// ---------------- scratch (device globals: allocation-free rule) -------------
static __device__ float g_xp[(size_t)BB * 5 * UU];            // 4096 x 2560 f32
static __device__ float g_rp[(size_t)BB * 3 * UU];            // 4096 x 1536 f32

static __device__ bf16 g_xhi[(size_t)BB * DD];
static __device__ bf16 g_xlo[(size_t)BB * DD];
static __device__ bf16 g_hhi[(size_t)BB * UU];
static __device__ bf16 g_hlo[(size_t)BB * UU];
static __device__ bf16 g_whi[(size_t)DD * 5 * UU];            // [256][2560] K-major
static __device__ bf16 g_wlo[(size_t)DD * 5 * UU];
static __device__ bf16 g_rhi[(size_t)UU * 3 * UU];            // [512][1536]
static __device__ bf16 g_rlo[(size_t)UU * 3 * UU];

// ---------------- PTX helpers ----------------
__device__ __forceinline__ uint32_t smem_u32(const void* p) {
    uint32_t a;
    asm("{ .reg .u64 t; cvta.to.shared.u64 t, %1; cvt.u32.u64 %0, t; }"
        : "=r"(a) : "l"(p));
    return a;
}
__device__ __forceinline__ void cp16(uint32_t saddr, const void* gaddr) {
    asm volatile("cp.async.cg.shared.global [%0], [%1], 16;"
                 :: "r"(saddr), "l"(gaddr) : "memory");
}
#define CP_COMMIT() asm volatile("cp.async.commit_group;" ::: "memory")
#define CP_WAIT(n)  asm volatile("cp.async.wait_group %0;" :: "n"(n) : "memory")

__device__ __forceinline__ void ldm_x4(uint32_t* r, uint32_t addr) {
    asm volatile("ldmatrix.sync.aligned.m8n8.x4.shared.b16 {%0,%1,%2,%3}, [%4];"
                 : "=r"(r[0]), "=r"(r[1]), "=r"(r[2]), "=r"(r[3]) : "r"(addr));
}
__device__ __forceinline__ void ldm_x4t(uint32_t* r, uint32_t addr) {
    asm volatile("ldmatrix.sync.aligned.m8n8.x4.trans.shared.b16 {%0,%1,%2,%3}, [%4];"
                 : "=r"(r[0]), "=r"(r[1]), "=r"(r[2]), "=r"(r[3]) : "r"(addr));
}
__device__ __forceinline__ void mma_bf16(float* d, const uint32_t* a, const uint32_t* b) {
    asm volatile("mma.sync.aligned.m16n8k16.row.col.f32.bf16.bf16.f32 "
                 "{%0,%1,%2,%3}, {%4,%5,%6,%7}, {%8,%9}, {%0,%1,%2,%3};"
                 : "+f"(d[0]), "+f"(d[1]), "+f"(d[2]), "+f"(d[3])
                 : "r"(a[0]), "r"(a[1]), "r"(a[2]), "r"(a[3]), "r"(b[0]), "r"(b[1]));
}

// ---------------- fused vectorized fp32 -> bf16 hi/lo split ------------------
// One launch covers all four tensors; each thread handles 4 floats.
#define NV0 (BB * DD / 4)
#define NV1 (NV0 + BB * UU / 4)
#define NV2 (NV1 + DD * 5 * UU / 4)
#define NV3 (NV2 + UU * 3 * UU / 4)

__global__ __launch_bounds__(256)
void split_all(const float* __restrict__ x, const float* __restrict__ h0,
               const float* __restrict__ w, const float* __restrict__ r,
               bf16* __restrict__ xhi, bf16* __restrict__ xlo,
               bf16* __restrict__ hhi, bf16* __restrict__ hlo,
               bf16* __restrict__ whi, bf16* __restrict__ wlo,
               bf16* __restrict__ rhi, bf16* __restrict__ rlo) {
    int i = blockIdx.x * 256 + threadIdx.x;          // vec4 index
    const float* src; bf16* hi; bf16* lo; int off;
    if (i < NV0)      { src = x;  hi = xhi; lo = xlo; off = i; }
    else if (i < NV1) { src = h0; hi = hhi; lo = hlo; off = i - NV0; }
    else if (i < NV2) { src = w;  hi = whi; lo = wlo; off = i - NV1; }
    else              { src = r;  hi = rhi; lo = rlo; off = i - NV2; }

    float4 v = ((const float4*)src)[off];
    bf16 h0v = __float2bfloat16(v.x), h1v = __float2bfloat16(v.y);
    bf16 h2v = __float2bfloat16(v.z), h3v = __float2bfloat16(v.w);
    bf16 l0v = __float2bfloat16(v.x - __bfloat162float(h0v));
    bf16 l1v = __float2bfloat16(v.y - __bfloat162float(h1v));
    bf16 l2v = __float2bfloat16(v.z - __bfloat162float(h2v));
    bf16 l3v = __float2bfloat16(v.w - __bfloat162float(h3v));

    __nv_bfloat162* hp = (__nv_bfloat162*)(hi) + off * 2;
    __nv_bfloat162* lp = (__nv_bfloat162*)(lo) + off * 2;
    hp[0] = __nv_bfloat162(h0v, h1v);
    hp[1] = __nv_bfloat162(h2v, h3v);
    lp[0] = __nv_bfloat162(l0v, l1v);
    lp[1] = __nv_bfloat162(l2v, l3v);
}

// ---------------- HMMA GEMM tile: 128x128, hi/lo 3-phase K loop --------------
#define APAD 8
#define BPAD 8
#define A_ROWW (32 + APAD)          // bf16 elems per A smem row
#define B_ROWW (128 + BPAD)

template<int K, int NTOT, int SEL>
__device__ __forceinline__
void gemm_tile(int bm, int bn,
               const bf16* __restrict__ Ahi, const bf16* __restrict__ Alo,
               const bf16* __restrict__ Bhi, const bf16* __restrict__ Blo,
               bf16 (&As)[2][128][A_ROWW], bf16 (&Bs)[2][32][B_ROWW]) {
    float* __restrict__ C = (SEL == 0) ? g_xp : g_rp;

    const int tid = threadIdx.x;
    const int wid = tid >> 5, lane = tid & 31;
    const int wm = wid >> 2, wn = wid & 3;                 // 2 x 4 warp grid

    const int aRow = tid >> 2;          // 0..63 (+64)
    const int aSeg = tid & 3;
    const int bRow = tid >> 4;          // 0..15 (+16)
    const int bSeg = tid & 15;

    constexpr int KCH = K / 32;
    constexpr int NC  = 3 * KCH;

    const uint32_t sA0 = smem_u32(&As[0][0][0]);
    const uint32_t sB0 = smem_u32(&Bs[0][0][0]);
    constexpr uint32_t A_BUF = 128 * A_ROWW * 2;
    constexpr uint32_t B_BUF = 32 * B_ROWW * 2;
    constexpr uint32_t A_ROW = A_ROWW * 2;                 // 80 B
    constexpr uint32_t B_ROW = B_ROWW * 2;                 // 272 B

    auto load_chunk = [&](int kc, int buf) {
        const int p  = kc / KCH;
        const int kk = kc - p * KCH;
        const bf16* Asrc = (p == 2) ? Alo : Ahi;
        const bf16* Bsrc = (p == 1) ? Blo : Bhi;
        const bf16* ag = Asrc + (size_t)(bm * 128 + aRow) * K + kk * 32 + aSeg * 8;
        uint32_t sa = sA0 + buf * A_BUF + aRow * A_ROW + aSeg * 16;
        cp16(sa, ag);
        cp16(sa + 64 * A_ROW, ag + (size_t)64 * K);
        const bf16* bg = Bsrc + (size_t)(kk * 32 + bRow) * NTOT + bn * 128 + bSeg * 8;
        uint32_t sb = sB0 + buf * B_BUF + bRow * B_ROW + bSeg * 16;
        cp16(sb, bg);
        cp16(sb + 16 * B_ROW, bg + (size_t)16 * NTOT);
        CP_COMMIT();
    };

    float acc[4][4][4];
    #pragma unroll
    for (int i = 0; i < 4; i++)
        #pragma unroll
        for (int j = 0; j < 4; j++)
            #pragma unroll
            for (int v = 0; v < 4; v++) acc[i][j][v] = 0.0f;

    load_chunk(0, 0);

    const int lrow = lane & 15;
    const int lhalf = lane >> 4;

    for (int kc = 0; kc < NC; ++kc) {
        if (kc + 1 < NC) { load_chunk(kc + 1, (kc + 1) & 1); CP_WAIT(1); }
        else             { CP_WAIT(0); }
        __syncthreads();

        const int buf = kc & 1;
        const uint32_t aBase = sA0 + buf * A_BUF;
        const uint32_t bBase = sB0 + buf * B_BUF;

        #pragma unroll
        for (int ks = 0; ks < 32; ks += 16) {
            uint32_t afr[4][4];
            #pragma unroll
            for (int mf = 0; mf < 4; mf++) {
                uint32_t addr = aBase + (wm * 64 + mf * 16 + lrow) * A_ROW
                              + (ks + lhalf * 8) * 2;
                ldm_x4(afr[mf], addr);
            }
            uint32_t bfr[4][2];
            #pragma unroll
            for (int nh = 0; nh < 2; nh++) {
                uint32_t addr = bBase + (ks + lrow) * B_ROW
                              + (wn * 32 + nh * 16 + lhalf * 8) * 2;
                uint32_t r[4];
                ldm_x4t(r, addr);
                bfr[2 * nh][0] = r[0]; bfr[2 * nh][1] = r[1];
                bfr[2 * nh + 1][0] = r[2]; bfr[2 * nh + 1][1] = r[3];
            }
            #pragma unroll
            for (int mf = 0; mf < 4; mf++)
                #pragma unroll
                for (int nf = 0; nf < 4; nf++)
                    mma_bf16(acc[mf][nf], afr[mf], bfr[nf]);
        }
        __syncthreads();
    }

    const int g = lane >> 2, q = lane & 3;
    #pragma unroll
    for (int mf = 0; mf < 4; mf++) {
        const int row0 = bm * 128 + wm * 64 + mf * 16 + g;
        #pragma unroll
        for (int nf = 0; nf < 4; nf++) {
            const int col = bn * 128 + wn * 32 + nf * 8 + q * 2;
            float2 v0 = make_float2(acc[mf][nf][0], acc[mf][nf][1]);
            float2 v1 = make_float2(acc[mf][nf][2], acc[mf][nf][3]);
            *(float2*)(C + (size_t)row0 * NTOT + col)       = v0;
            *(float2*)(C + (size_t)(row0 + 8) * NTOT + col) = v1;
        }
    }
}

// Merged launch: GEMM2 tiles (longer: K=512 -> 48 chunks) first for LPT packing,
// then GEMM1 tiles (K=256 -> 24 chunks). One wave structure instead of two.
#define G2_TILES (3 * UU / 128 * (BB / 128))    // 12 * 32 = 384
#define G1_TILES (5 * UU / 128 * (BB / 128))    // 20 * 32 = 640

__global__ __launch_bounds__(256)
void hmma_both(const bf16* __restrict__ xhi, const bf16* __restrict__ xlo,
               const bf16* __restrict__ whi, const bf16* __restrict__ wlo,
               const bf16* __restrict__ hhi, const bf16* __restrict__ hlo,
               const bf16* __restrict__ rhi, const bf16* __restrict__ rlo) {
    __shared__ __align__(16) bf16 As[2][128][A_ROWW];
    __shared__ __align__(16) bf16 Bs[2][32][B_ROWW];

    const int bid = blockIdx.x;
    if (bid < G2_TILES) {
        const int bm = bid / 12, bn = bid % 12;
        gemm_tile<UU, 3 * UU, 1>(bm, bn, hhi, hlo, rhi, rlo, As, Bs);
    } else {
        const int b1 = bid - G2_TILES;
        const int bm = b1 / 20, bn = b1 % 20;
        gemm_tile<DD, 5 * UU, 0>(bm, bn, xhi, xlo, whi, wlo, As, Bs);
    }
}

// ---------------- fused elementwise LSTM epilogue ----------------
__device__ __forceinline__ float sigf(float x) { return 1.0f / (1.0f + __expf(-x)); }

struct F4v { float v[4]; };
__device__ __forceinline__ F4v ld4(const float* p) {
    float4 t = *(const float4*)p;
    F4v r; r.v[0] = t.x; r.v[1] = t.y; r.v[2] = t.z; r.v[3] = t.w;
    return r;
}

__global__ __launch_bounds__(256)
void eltwise(const float* __restrict__ t, const float* __restrict__ c0,
             const float* __restrict__ ktime, float* __restrict__ out) {
    int idx = blockIdx.x * 256 + threadIdx.x;
    int b = idx >> 7;
    int u = (idx & 127) << 2;

    const float tb = __ldg(&t[b]);
    const float* xp = g_xp + (size_t)b * (5 * UU) + u;
    const float* rp = g_rp + (size_t)b * (3 * UU) + u;

    F4v xi  = ld4(xp + 0 * UU);
    F4v xc  = ld4(xp + 1 * UU);
    F4v xo  = ld4(xp + 2 * UU);
    F4v xt1 = ld4(xp + 3 * UU);
    F4v xt2 = ld4(xp + 4 * UU);
    F4v ri  = ld4(rp + 0 * UU);
    F4v rc  = ld4(rp + 1 * UU);
    F4v ro  = ld4(rp + 2 * UU);
    F4v c0v = ld4(c0 + (size_t)b * UU + u);
    F4v k1  = ld4(ktime + 0 * UU + u);
    F4v k2  = ld4(ktime + 1 * UU + u);
    F4v ko  = ld4(ktime + 2 * UU + u);

    float hv[4], cmv[4];
    #pragma unroll
    for (int j = 0; j < 4; j++) {
        float i_g = sigf(xi.v[j] + ri.v[j]);
        float t1  = sigf(xt1.v[j] + sigf(tb * k1.v[j]));
        float t1c = (t1 > -1e-5f) ? -1e-5f : t1;
        float t2  = sigf(xt2.v[j] + sigf(tb * k2.v[j]));
        float ct  = tanhf(xc.v[j] + rc.v[j]);
        float cm_ = (1.0f - i_g * t1) * c0v.v[j] + i_g * ct * t1c;
        float cm  = (1.0f - i_g) * c0v.v[j] + i_g * ct * t2;
        float o   = sigf(xo.v[j] + ro.v[j] + tb * ko.v[j]);
        hv[j]  = tanhf(cm_) * o;
        cmv[j] = cm;
    }

    float* hout = out + (size_t)b * UU + u;
    float* cout = out + (size_t)BB * UU + (size_t)b * UU + u;
    *(float4*)hout = make_float4(hv[0], hv[1], hv[2], hv[3]);
    *(float4*)cout = make_float4(cmv[0], cmv[1], cmv[2], cmv[3]);
}

// ---------------- launch ----------------
extern "C" void kernel_launch(void* const* d_in, const int* in_sizes, int n_in,
                              void* d_out, int out_size) {
    const float* x     = (const float*)d_in[0];
    const float* t     = (const float*)d_in[1];
    const float* h0    = (const float*)d_in[2];
    const float* c0    = (const float*)d_in[3];
    const float* kern  = (const float*)d_in[4];
    const float* rkern = (const float*)d_in[5];
    const float* ktime = (const float*)d_in[6];
    float* out = (float*)d_out;

    bf16 *xhi, *xlo, *hhi, *hlo, *whi, *wlo, *rhi, *rlo;
    cudaGetSymbolAddress((void**)&xhi, g_xhi);
    cudaGetSymbolAddress((void**)&xlo, g_xlo);
    cudaGetSymbolAddress((void**)&hhi, g_hhi);
    cudaGetSymbolAddress((void**)&hlo, g_hlo);
    cudaGetSymbolAddress((void**)&whi, g_whi);
    cudaGetSymbolAddress((void**)&wlo, g_wlo);
    cudaGetSymbolAddress((void**)&rhi, g_rhi);
    cudaGetSymbolAddress((void**)&rlo, g_rlo);

    split_all<<<NV3 / 256, 256>>>(x, h0, kern, rkern,
                                  xhi, xlo, hhi, hlo, whi, wlo, rhi, rlo);

    hmma_both<<<G1_TILES + G2_TILES, 256>>>(xhi, xlo, whi, wlo,
                                            hhi, hlo, rhi, rlo);

    eltwise<<<(BB * UU / 4) / 256, 256>>>(t, c0, ktime, out);
}

// round 8
// speedup vs baseline: 2.9668x; 1.4059x over previous
#include <cuda_runtime.h>
#include <cuda_fp16.h>
#include <cstdint>

#define BB 4096
#define DD 256
#define UU 512

// ---------------- scratch (device globals: allocation-free rule) -------------
static __device__ float g_xp[(size_t)BB * 5 * UU];            // 4096 x 2560 f32
static __device__ float g_rp[(size_t)BB * 3 * UU];            // 4096 x 1536 f32

static __device__ __half g_xh[(size_t)BB * DD];               // A1 hi
static __device__ __half g_xl[(size_t)BB * DD];               // A1 lo
static __device__ __half g_hh[(size_t)BB * UU];               // A2 hi
static __device__ __half g_hl[(size_t)BB * UU];               // A2 lo
static __device__ __half g_wh[(size_t)DD * 5 * UU];           // B1 (hi only)
static __device__ __half g_rh[(size_t)UU * 3 * UU];           // B2 (hi only)

// ---------------- PTX helpers ----------------
__device__ __forceinline__ uint32_t smem_u32(const void* p) {
    uint32_t a;
    asm("{ .reg .u64 t; cvta.to.shared.u64 t, %1; cvt.u32.u64 %0, t; }"
        : "=r"(a) : "l"(p));
    return a;
}
__device__ __forceinline__ void cp16(uint32_t saddr, const void* gaddr) {
    asm volatile("cp.async.cg.shared.global [%0], [%1], 16;"
                 :: "r"(saddr), "l"(gaddr) : "memory");
}
#define CP_COMMIT() asm volatile("cp.async.commit_group;" ::: "memory")
#define CP_WAIT(n)  asm volatile("cp.async.wait_group %0;" :: "n"(n) : "memory")

__device__ __forceinline__ void ldm_x4(uint32_t* r, uint32_t addr) {
    asm volatile("ldmatrix.sync.aligned.m8n8.x4.shared.b16 {%0,%1,%2,%3}, [%4];"
                 : "=r"(r[0]), "=r"(r[1]), "=r"(r[2]), "=r"(r[3]) : "r"(addr));
}
__device__ __forceinline__ void ldm_x4t(uint32_t* r, uint32_t addr) {
    asm volatile("ldmatrix.sync.aligned.m8n8.x4.trans.shared.b16 {%0,%1,%2,%3}, [%4];"
                 : "=r"(r[0]), "=r"(r[1]), "=r"(r[2]), "=r"(r[3]) : "r"(addr));
}
__device__ __forceinline__ void mma_f16(float* d, const uint32_t* a, const uint32_t* b) {
    asm volatile("mma.sync.aligned.m16n8k16.row.col.f32.f16.f16.f32 "
                 "{%0,%1,%2,%3}, {%4,%5,%6,%7}, {%8,%9}, {%0,%1,%2,%3};"
                 : "+f"(d[0]), "+f"(d[1]), "+f"(d[2]), "+f"(d[3])
                 : "r"(a[0]), "r"(a[1]), "r"(a[2]), "r"(a[3]), "r"(b[0]), "r"(b[1]));
}

// ---------------- fused vectorized fp32 -> fp16 split ------------------------
// x, h0: hi + lo (residual). kernel, rkern: hi only.
#define NV0 (BB * DD / 4)
#define NV1 (NV0 + BB * UU / 4)
#define NV2 (NV1 + DD * 5 * UU / 4)
#define NV3 (NV2 + UU * 3 * UU / 4)

__global__ __launch_bounds__(256)
void split_all(const float* __restrict__ x, const float* __restrict__ h0,
               const float* __restrict__ w, const float* __restrict__ r,
               __half* __restrict__ xh, __half* __restrict__ xl,
               __half* __restrict__ hh, __half* __restrict__ hl,
               __half* __restrict__ wh, __half* __restrict__ rh) {
    int i = blockIdx.x * 256 + threadIdx.x;          // vec4 index
    const float* src; __half* hi; __half* lo; int off; bool wantLo;
    if (i < NV0)      { src = x;  hi = xh; lo = xl; off = i;       wantLo = true; }
    else if (i < NV1) { src = h0; hi = hh; lo = hl; off = i - NV0; wantLo = true; }
    else if (i < NV2) { src = w;  hi = wh; lo = 0;  off = i - NV1; wantLo = false; }
    else              { src = r;  hi = rh; lo = 0;  off = i - NV2; wantLo = false; }

    float4 v = ((const float4*)src)[off];
    __half a0 = __float2half(v.x), a1 = __float2half(v.y);
    __half a2 = __float2half(v.z), a3 = __float2half(v.w);
    __half2* hp = (__half2*)(hi) + off * 2;
    hp[0] = __half2(a0, a1);
    hp[1] = __half2(a2, a3);
    if (wantLo) {
        __half l0 = __float2half(v.x - __half2float(a0));
        __half l1 = __float2half(v.y - __half2float(a1));
        __half l2 = __float2half(v.z - __half2float(a2));
        __half l3 = __float2half(v.w - __half2float(a3));
        __half2* lp = (__half2*)(lo) + off * 2;
        lp[0] = __half2(l0, l1);
        lp[1] = __half2(l2, l3);
    }
}

// ---------------- HMMA GEMM tile: 128x128, fp16 2-phase (Ah+Al)*Bh -----------
#define APAD 8
#define BPAD 8
#define A_ROWW (32 + APAD)          // half elems per A smem row (80 B)
#define B_ROWW (128 + BPAD)         // 272 B

// dynamic smem layout (bytes):
//   [0, A_BUF*2)              Ah double buffer
//   [A_BUF*2, A_BUF*4)        Al double buffer
//   [A_BUF*4, A_BUF*4+B_BUF*2) Bh double buffer
#define A_BUF (128 * A_ROWW * 2)    // 10240 B
#define B_BUF (32 * B_ROWW * 2)     // 8704 B
#define SMEM_TOTAL (4 * A_BUF + 2 * B_BUF)   // 58368 B

template<int K, int NTOT, int SEL>
__device__ __forceinline__
void gemm_tile(int bm, int bn, uint32_t sbase,
               const __half* __restrict__ Ahi, const __half* __restrict__ Alo,
               const __half* __restrict__ Bh) {
    float* __restrict__ C = (SEL == 0) ? g_xp : g_rp;

    const int tid = threadIdx.x;
    const int wid = tid >> 5, lane = tid & 31;
    const int wm = wid >> 2, wn = wid & 3;                 // 2 x 4 warp grid

    const int aRow = tid >> 2;          // 0..63 (+64)
    const int aSeg = tid & 3;
    const int bRow = tid >> 4;          // 0..15 (+16)
    const int bSeg = tid & 15;

    constexpr int KCH = K / 32;

    const uint32_t sAh0 = sbase;
    const uint32_t sAl0 = sbase + 2 * A_BUF;
    const uint32_t sB0  = sbase + 4 * A_BUF;
    constexpr uint32_t A_ROW = A_ROWW * 2;                 // 80 B
    constexpr uint32_t B_ROW = B_ROWW * 2;                 // 272 B

    auto load_chunk = [&](int kk, int buf) {
        const __half* agh = Ahi + (size_t)(bm * 128 + aRow) * K + kk * 32 + aSeg * 8;
        const __half* agl = Alo + (size_t)(bm * 128 + aRow) * K + kk * 32 + aSeg * 8;
        uint32_t sao = buf * A_BUF + aRow * A_ROW + aSeg * 16;
        cp16(sAh0 + sao, agh);
        cp16(sAh0 + sao + 64 * A_ROW, agh + (size_t)64 * K);
        cp16(sAl0 + sao, agl);
        cp16(sAl0 + sao + 64 * A_ROW, agl + (size_t)64 * K);
        const __half* bg = Bh + (size_t)(kk * 32 + bRow) * NTOT + bn * 128 + bSeg * 8;
        uint32_t sb = sB0 + buf * B_BUF + bRow * B_ROW + bSeg * 16;
        cp16(sb, bg);
        cp16(sb + 16 * B_ROW, bg + (size_t)16 * NTOT);
        CP_COMMIT();
    };

    float acc[4][4][4];
    #pragma unroll
    for (int i = 0; i < 4; i++)
        #pragma unroll
        for (int j = 0; j < 4; j++)
            #pragma unroll
            for (int v = 0; v < 4; v++) acc[i][j][v] = 0.0f;

    load_chunk(0, 0);

    const int lrow = lane & 15;
    const int lhalf = lane >> 4;

    for (int kc = 0; kc < KCH; ++kc) {
        if (kc + 1 < KCH) { load_chunk(kc + 1, (kc + 1) & 1); CP_WAIT(1); }
        else              { CP_WAIT(0); }
        __syncthreads();

        const int buf = kc & 1;
        const uint32_t ahBase = sAh0 + buf * A_BUF;
        const uint32_t alBase = sAl0 + buf * A_BUF;
        const uint32_t bBase  = sB0 + buf * B_BUF;

        #pragma unroll
        for (int ks = 0; ks < 32; ks += 16) {
            // B fragments loaded once, reused for both A phases
            uint32_t bfr[4][2];
            #pragma unroll
            for (int nh = 0; nh < 2; nh++) {
                uint32_t addr = bBase + (ks + lrow) * B_ROW
                              + (wn * 32 + nh * 16 + lhalf * 8) * 2;
                uint32_t r[4];
                ldm_x4t(r, addr);
                bfr[2 * nh][0] = r[0]; bfr[2 * nh][1] = r[1];
                bfr[2 * nh + 1][0] = r[2]; bfr[2 * nh + 1][1] = r[3];
            }
            // phase 0: Ah * Bh
            uint32_t afr[4][4];
            #pragma unroll
            for (int mf = 0; mf < 4; mf++) {
                uint32_t addr = ahBase + (wm * 64 + mf * 16 + lrow) * A_ROW
                              + (ks + lhalf * 8) * 2;
                ldm_x4(afr[mf], addr);
            }
            #pragma unroll
            for (int mf = 0; mf < 4; mf++)
                #pragma unroll
                for (int nf = 0; nf < 4; nf++)
                    mma_f16(acc[mf][nf], afr[mf], bfr[nf]);
            // phase 1: Al * Bh (same B fragments)
            #pragma unroll
            for (int mf = 0; mf < 4; mf++) {
                uint32_t addr = alBase + (wm * 64 + mf * 16 + lrow) * A_ROW
                              + (ks + lhalf * 8) * 2;
                ldm_x4(afr[mf], addr);
            }
            #pragma unroll
            for (int mf = 0; mf < 4; mf++)
                #pragma unroll
                for (int nf = 0; nf < 4; nf++)
                    mma_f16(acc[mf][nf], afr[mf], bfr[nf]);
        }
        __syncthreads();
    }

    const int g = lane >> 2, q = lane & 3;
    #pragma unroll
    for (int mf = 0; mf < 4; mf++) {
        const int row0 = bm * 128 + wm * 64 + mf * 16 + g;
        #pragma unroll
        for (int nf = 0; nf < 4; nf++) {
            const int col = bn * 128 + wn * 32 + nf * 8 + q * 2;
            float2 v0 = make_float2(acc[mf][nf][0], acc[mf][nf][1]);
            float2 v1 = make_float2(acc[mf][nf][2], acc[mf][nf][3]);
            *(float2*)(C + (size_t)row0 * NTOT + col)       = v0;
            *(float2*)(C + (size_t)(row0 + 8) * NTOT + col) = v1;
        }
    }
}

// Merged launch: GEMM2 tiles (K=512, longer) first for LPT packing.
#define G2_TILES (3 * UU / 128 * (BB / 128))    // 384
#define G1_TILES (5 * UU / 128 * (BB / 128))    // 640

__global__ __launch_bounds__(256)
void hmma_both(const __half* __restrict__ xh, const __half* __restrict__ xl,
               const __half* __restrict__ wh,
               const __half* __restrict__ hh, const __half* __restrict__ hl,
               const __half* __restrict__ rh) {
    extern __shared__ __align__(16) char dynsmem[];
    const uint32_t sbase = smem_u32(dynsmem);

    const int bid = blockIdx.x;
    if (bid < G2_TILES) {
        const int bm = bid / 12, bn = bid % 12;
        gemm_tile<UU, 3 * UU, 1>(bm, bn, sbase, hh, hl, rh);
    } else {
        const int b1 = bid - G2_TILES;
        const int bm = b1 / 20, bn = b1 % 20;
        gemm_tile<DD, 5 * UU, 0>(bm, bn, sbase, xh, xl, wh);
    }
}

// ---------------- fused elementwise LSTM epilogue ----------------
__device__ __forceinline__ float sigf(float x) { return 1.0f / (1.0f + __expf(-x)); }

struct F4v { float v[4]; };
__device__ __forceinline__ F4v ld4(const float* p) {
    float4 t = *(const float4*)p;
    F4v r; r.v[0] = t.x; r.v[1] = t.y; r.v[2] = t.z; r.v[3] = t.w;
    return r;
}

__global__ __launch_bounds__(256)
void eltwise(const float* __restrict__ t, const float* __restrict__ c0,
             const float* __restrict__ ktime, float* __restrict__ out) {
    int idx = blockIdx.x * 256 + threadIdx.x;
    int b = idx >> 7;
    int u = (idx & 127) << 2;

    const float tb = __ldg(&t[b]);
    const float* xp = g_xp + (size_t)b * (5 * UU) + u;
    const float* rp = g_rp + (size_t)b * (3 * UU) + u;

    F4v xi  = ld4(xp + 0 * UU);
    F4v xc  = ld4(xp + 1 * UU);
    F4v xo  = ld4(xp + 2 * UU);
    F4v xt1 = ld4(xp + 3 * UU);
    F4v xt2 = ld4(xp + 4 * UU);
    F4v ri  = ld4(rp + 0 * UU);
    F4v rc  = ld4(rp + 1 * UU);
    F4v ro  = ld4(rp + 2 * UU);
    F4v c0v = ld4(c0 + (size_t)b * UU + u);
    F4v k1  = ld4(ktime + 0 * UU + u);
    F4v k2  = ld4(ktime + 1 * UU + u);
    F4v ko  = ld4(ktime + 2 * UU + u);

    float hv[4], cmv[4];
    #pragma unroll
    for (int j = 0; j < 4; j++) {
        float i_g = sigf(xi.v[j] + ri.v[j]);
        float t1  = sigf(xt1.v[j] + sigf(tb * k1.v[j]));
        float t1c = (t1 > -1e-5f) ? -1e-5f : t1;
        float t2  = sigf(xt2.v[j] + sigf(tb * k2.v[j]));
        float ct  = tanhf(xc.v[j] + rc.v[j]);
        float cm_ = (1.0f - i_g * t1) * c0v.v[j] + i_g * ct * t1c;
        float cm  = (1.0f - i_g) * c0v.v[j] + i_g * ct * t2;
        float o   = sigf(xo.v[j] + ro.v[j] + tb * ko.v[j]);
        hv[j]  = tanhf(cm_) * o;
        cmv[j] = cm;
    }

    float* hout = out + (size_t)b * UU + u;
    float* cout = out + (size_t)BB * UU + (size_t)b * UU + u;
    *(float4*)hout = make_float4(hv[0], hv[1], hv[2], hv[3]);
    *(float4*)cout = make_float4(cmv[0], cmv[1], cmv[2], cmv[3]);
}

// ---------------- launch ----------------
extern "C" void kernel_launch(void* const* d_in, const int* in_sizes, int n_in,
                              void* d_out, int out_size) {
    const float* x     = (const float*)d_in[0];
    const float* t     = (const float*)d_in[1];
    const float* h0    = (const float*)d_in[2];
    const float* c0    = (const float*)d_in[3];
    const float* kern  = (const float*)d_in[4];
    const float* rkern = (const float*)d_in[5];
    const float* ktime = (const float*)d_in[6];
    float* out = (float*)d_out;

    __half *xh, *xl, *hh, *hl, *wh, *rh;
    cudaGetSymbolAddress((void**)&xh, g_xh);
    cudaGetSymbolAddress((void**)&xl, g_xl);
    cudaGetSymbolAddress((void**)&hh, g_hh);
    cudaGetSymbolAddress((void**)&hl, g_hl);
    cudaGetSymbolAddress((void**)&wh, g_wh);
    cudaGetSymbolAddress((void**)&rh, g_rh);

    cudaFuncSetAttribute(hmma_both,
                         cudaFuncAttributeMaxDynamicSharedMemorySize, SMEM_TOTAL);

    split_all<<<NV3 / 256, 256>>>(x, h0, kern, rkern, xh, xl, hh, hl, wh, rh);

    hmma_both<<<G1_TILES + G2_TILES, 256, SMEM_TOTAL>>>(xh, xl, wh, hh, hl, rh);

    eltwise<<<(BB * UU / 4) / 256, 256>>>(t, c0, ktime, out);
}

// round 9
// speedup vs baseline: 3.1880x; 1.0746x over previous
#include <cuda_runtime.h>
#include <cuda_fp16.h>
#include <cstdint>

#define BB 4096
#define DD 256
#define UU 512

// ---------------- scratch (device globals: allocation-free rule) -------------
static __device__ float g_xp[(size_t)BB * 5 * UU];            // 4096 x 2560 f32
static __device__ float g_rp[(size_t)BB * 3 * UU];            // 4096 x 1536 f32

static __device__ __half g_xh[(size_t)BB * DD];               // A1 hi
static __device__ __half g_xl[(size_t)BB * DD];               // A1 lo
static __device__ __half g_hh[(size_t)BB * UU];               // A2 hi
static __device__ __half g_hl[(size_t)BB * UU];               // A2 lo
static __device__ __half g_wh[(size_t)DD * 5 * UU];           // B1 (hi only)
static __device__ __half g_rh[(size_t)UU * 3 * UU];           // B2 (hi only)

// ---------------- PTX helpers ----------------
__device__ __forceinline__ uint32_t smem_u32(const void* p) {
    uint32_t a;
    asm("{ .reg .u64 t; cvta.to.shared.u64 t, %1; cvt.u32.u64 %0, t; }"
        : "=r"(a) : "l"(p));
    return a;
}
__device__ __forceinline__ void cp16(uint32_t saddr, const void* gaddr) {
    asm volatile("cp.async.cg.shared.global [%0], [%1], 16;"
                 :: "r"(saddr), "l"(gaddr) : "memory");
}
#define CP_COMMIT() asm volatile("cp.async.commit_group;" ::: "memory")
#define CP_WAIT(n)  asm volatile("cp.async.wait_group %0;" :: "n"(n) : "memory")

__device__ __forceinline__ void ldm_x4(uint32_t* r, uint32_t addr) {
    asm volatile("ldmatrix.sync.aligned.m8n8.x4.shared.b16 {%0,%1,%2,%3}, [%4];"
                 : "=r"(r[0]), "=r"(r[1]), "=r"(r[2]), "=r"(r[3]) : "r"(addr));
}
__device__ __forceinline__ void ldm_x4t(uint32_t* r, uint32_t addr) {
    asm volatile("ldmatrix.sync.aligned.m8n8.x4.trans.shared.b16 {%0,%1,%2,%3}, [%4];"
                 : "=r"(r[0]), "=r"(r[1]), "=r"(r[2]), "=r"(r[3]) : "r"(addr));
}
__device__ __forceinline__ void mma_f16(float* d, const uint32_t* a, const uint32_t* b) {
    asm volatile("mma.sync.aligned.m16n8k16.row.col.f32.f16.f16.f32 "
                 "{%0,%1,%2,%3}, {%4,%5,%6,%7}, {%8,%9}, {%0,%1,%2,%3};"
                 : "+f"(d[0]), "+f"(d[1]), "+f"(d[2]), "+f"(d[3])
                 : "r"(a[0]), "r"(a[1]), "r"(a[2]), "r"(a[3]), "r"(b[0]), "r"(b[1]));
}

// ---------------- fused vectorized fp32 -> fp16 split ------------------------
#define NV0 (BB * DD / 4)
#define NV1 (NV0 + BB * UU / 4)
#define NV2 (NV1 + DD * 5 * UU / 4)
#define NV3 (NV2 + UU * 3 * UU / 4)

__global__ __launch_bounds__(256)
void split_all(const float* __restrict__ x, const float* __restrict__ h0,
               const float* __restrict__ w, const float* __restrict__ r,
               __half* __restrict__ xh, __half* __restrict__ xl,
               __half* __restrict__ hh, __half* __restrict__ hl,
               __half* __restrict__ wh, __half* __restrict__ rh) {
    int i = blockIdx.x * 256 + threadIdx.x;          // vec4 index
    const float* src; __half* hi; __half* lo; int off; bool wantLo;
    if (i < NV0)      { src = x;  hi = xh; lo = xl; off = i;       wantLo = true; }
    else if (i < NV1) { src = h0; hi = hh; lo = hl; off = i - NV0; wantLo = true; }
    else if (i < NV2) { src = w;  hi = wh; lo = 0;  off = i - NV1; wantLo = false; }
    else              { src = r;  hi = rh; lo = 0;  off = i - NV2; wantLo = false; }

    float4 v = ((const float4*)src)[off];
    __half a0 = __float2half(v.x), a1 = __float2half(v.y);
    __half a2 = __float2half(v.z), a3 = __float2half(v.w);
    __half2* hp = (__half2*)(hi) + off * 2;
    hp[0] = __half2(a0, a1);
    hp[1] = __half2(a2, a3);
    if (wantLo) {
        __half l0 = __float2half(v.x - __half2float(a0));
        __half l1 = __float2half(v.y - __half2float(a1));
        __half l2 = __float2half(v.z - __half2float(a2));
        __half l3 = __float2half(v.w - __half2float(a3));
        __half2* lp = (__half2*)(lo) + off * 2;
        lp[0] = __half2(l0, l1);
        lp[1] = __half2(l2, l3);
    }
}

// ---------------- HMMA GEMM tile: 128x128, fp16 2-phase (Ah+Al)*Bh -----------
// 3-stage cp.async pipeline, 2 CTAs/SM.
#define APAD 8
#define BPAD 8
#define A_ROWW (32 + APAD)          // half elems per A smem row (80 B)
#define B_ROWW (128 + BPAD)         // 272 B

#define A_BUF (128 * A_ROWW * 2)    // 10240 B (one A tile)
#define B_BUF (32 * B_ROWW * 2)     // 8704 B
// stage layout: Ah @0, Al @A_BUF, B @2*A_BUF
#define STAGE_B (2 * A_BUF + B_BUF) // 29184 B
#define NSTAGE 3
#define SMEM_TOTAL (NSTAGE * STAGE_B)   // 87552 B

template<int K, int NTOT, int SEL>
__device__ __forceinline__
void gemm_tile(int bm, int bn, uint32_t sbase,
               const __half* __restrict__ Ahi, const __half* __restrict__ Alo,
               const __half* __restrict__ Bh) {
    float* __restrict__ C = (SEL == 0) ? g_xp : g_rp;

    const int tid = threadIdx.x;
    const int wid = tid >> 5, lane = tid & 31;
    const int wm = wid >> 2, wn = wid & 3;                 // 2 x 4 warp grid

    const int aRow = tid >> 2;          // 0..63 (+64)
    const int aSeg = tid & 3;
    const int bRow = tid >> 4;          // 0..15 (+16)
    const int bSeg = tid & 15;

    constexpr int KCH = K / 32;
    constexpr uint32_t A_ROW = A_ROWW * 2;                 // 80 B
    constexpr uint32_t B_ROW = B_ROWW * 2;                 // 272 B

    auto load_chunk = [&](int kk, int stage) {
        const uint32_t st = sbase + stage * STAGE_B;
        const __half* agh = Ahi + (size_t)(bm * 128 + aRow) * K + kk * 32 + aSeg * 8;
        const __half* agl = Alo + (size_t)(bm * 128 + aRow) * K + kk * 32 + aSeg * 8;
        uint32_t sao = aRow * A_ROW + aSeg * 16;
        cp16(st + sao, agh);
        cp16(st + sao + 64 * A_ROW, agh + (size_t)64 * K);
        cp16(st + A_BUF + sao, agl);
        cp16(st + A_BUF + sao + 64 * A_ROW, agl + (size_t)64 * K);
        const __half* bg = Bh + (size_t)(kk * 32 + bRow) * NTOT + bn * 128 + bSeg * 8;
        uint32_t sb = st + 2 * A_BUF + bRow * B_ROW + bSeg * 16;
        cp16(sb, bg);
        cp16(sb + 16 * B_ROW, bg + (size_t)16 * NTOT);
        CP_COMMIT();
    };

    float acc[4][4][4];
    #pragma unroll
    for (int i = 0; i < 4; i++)
        #pragma unroll
        for (int j = 0; j < 4; j++)
            #pragma unroll
            for (int v = 0; v < 4; v++) acc[i][j][v] = 0.0f;

    load_chunk(0, 0);
    load_chunk(1, 1);

    const int lrow = lane & 15;
    const int lhalf = lane >> 4;

    int stage = 0;             // stage holding chunk kc
    int nextStage = 2;         // stage to fill with chunk kc+2
    for (int kc = 0; kc < KCH; ++kc) {
        if (kc + 2 < KCH) {
            load_chunk(kc + 2, nextStage);
            CP_WAIT(2);
        } else if (kc + 1 < KCH) {
            CP_WAIT(1);
        } else {
            CP_WAIT(0);
        }
        __syncthreads();

        const uint32_t st = sbase + stage * STAGE_B;
        const uint32_t ahBase = st;
        const uint32_t alBase = st + A_BUF;
        const uint32_t bBase  = st + 2 * A_BUF;

        #pragma unroll
        for (int ks = 0; ks < 32; ks += 16) {
            // B fragments loaded once, reused for both A phases
            uint32_t bfr[4][2];
            #pragma unroll
            for (int nh = 0; nh < 2; nh++) {
                uint32_t addr = bBase + (ks + lrow) * B_ROW
                              + (wn * 32 + nh * 16 + lhalf * 8) * 2;
                uint32_t r[4];
                ldm_x4t(r, addr);
                bfr[2 * nh][0] = r[0]; bfr[2 * nh][1] = r[1];
                bfr[2 * nh + 1][0] = r[2]; bfr[2 * nh + 1][1] = r[3];
            }
            // phase 0: Ah * Bh
            uint32_t afr[4][4];
            #pragma unroll
            for (int mf = 0; mf < 4; mf++) {
                uint32_t addr = ahBase + (wm * 64 + mf * 16 + lrow) * A_ROW
                              + (ks + lhalf * 8) * 2;
                ldm_x4(afr[mf], addr);
            }
            #pragma unroll
            for (int mf = 0; mf < 4; mf++)
                #pragma unroll
                for (int nf = 0; nf < 4; nf++)
                    mma_f16(acc[mf][nf], afr[mf], bfr[nf]);
            // phase 1: Al * Bh (same B fragments)
            #pragma unroll
            for (int mf = 0; mf < 4; mf++) {
                uint32_t addr = alBase + (wm * 64 + mf * 16 + lrow) * A_ROW
                              + (ks + lhalf * 8) * 2;
                ldm_x4(afr[mf], addr);
            }
            #pragma unroll
            for (int mf = 0; mf < 4; mf++)
                #pragma unroll
                for (int nf = 0; nf < 4; nf++)
                    mma_f16(acc[mf][nf], afr[mf], bfr[nf]);
        }
        __syncthreads();

        stage = (stage + 1 == NSTAGE) ? 0 : stage + 1;
        nextStage = (nextStage + 1 == NSTAGE) ? 0 : nextStage + 1;
    }

    const int g = lane >> 2, q = lane & 3;
    #pragma unroll
    for (int mf = 0; mf < 4; mf++) {
        const int row0 = bm * 128 + wm * 64 + mf * 16 + g;
        #pragma unroll
        for (int nf = 0; nf < 4; nf++) {
            const int col = bn * 128 + wn * 32 + nf * 8 + q * 2;
            float2 v0 = make_float2(acc[mf][nf][0], acc[mf][nf][1]);
            float2 v1 = make_float2(acc[mf][nf][2], acc[mf][nf][3]);
            *(float2*)(C + (size_t)row0 * NTOT + col)       = v0;
            *(float2*)(C + (size_t)(row0 + 8) * NTOT + col) = v1;
        }
    }
}

// Merged launch: GEMM2 tiles (K=512, longer) first for LPT packing.
#define G2_TILES (3 * UU / 128 * (BB / 128))    // 384
#define G1_TILES (5 * UU / 128 * (BB / 128))    // 640

__global__ __launch_bounds__(256, 2)
void hmma_both(const __half* __restrict__ xh, const __half* __restrict__ xl,
               const __half* __restrict__ wh,
               const __half* __restrict__ hh, const __half* __restrict__ hl,
               const __half* __restrict__ rh) {
    extern __shared__ __align__(16) char dynsmem[];
    const uint32_t sbase = smem_u32(dynsmem);

    const int bid = blockIdx.x;
    if (bid < G2_TILES) {
        const int bm = bid / 12, bn = bid % 12;
        gemm_tile<UU, 3 * UU, 1>(bm, bn, sbase, hh, hl, rh);
    } else {
        const int b1 = bid - G2_TILES;
        const int bm = b1 / 20, bn = b1 % 20;
        gemm_tile<DD, 5 * UU, 0>(bm, bn, sbase, xh, xl, wh);
    }
}

// ---------------- fused elementwise LSTM epilogue ----------------
__device__ __forceinline__ float sigf(float x) { return 1.0f / (1.0f + __expf(-x)); }

struct F4v { float v[4]; };
__device__ __forceinline__ F4v ld4(const float* p) {
    float4 t = *(const float4*)p;
    F4v r; r.v[0] = t.x; r.v[1] = t.y; r.v[2] = t.z; r.v[3] = t.w;
    return r;
}

__global__ __launch_bounds__(256)
void eltwise(const float* __restrict__ t, const float* __restrict__ c0,
             const float* __restrict__ ktime, float* __restrict__ out) {
    int idx = blockIdx.x * 256 + threadIdx.x;
    int b = idx >> 7;
    int u = (idx & 127) << 2;

    const float tb = __ldg(&t[b]);
    const float* xp = g_xp + (size_t)b * (5 * UU) + u;
    const float* rp = g_rp + (size_t)b * (3 * UU) + u;

    F4v xi  = ld4(xp + 0 * UU);
    F4v xc  = ld4(xp + 1 * UU);
    F4v xo  = ld4(xp + 2 * UU);
    F4v xt1 = ld4(xp + 3 * UU);
    F4v xt2 = ld4(xp + 4 * UU);
    F4v ri  = ld4(rp + 0 * UU);
    F4v rc  = ld4(rp + 1 * UU);
    F4v ro  = ld4(rp + 2 * UU);
    F4v c0v = ld4(c0 + (size_t)b * UU + u);
    F4v k1  = ld4(ktime + 0 * UU + u);
    F4v k2  = ld4(ktime + 1 * UU + u);
    F4v ko  = ld4(ktime + 2 * UU + u);

    float hv[4], cmv[4];
    #pragma unroll
    for (int j = 0; j < 4; j++) {
        float i_g = sigf(xi.v[j] + ri.v[j]);
        float t1  = sigf(xt1.v[j] + sigf(tb * k1.v[j]));
        float t1c = (t1 > -1e-5f) ? -1e-5f : t1;
        float t2  = sigf(xt2.v[j] + sigf(tb * k2.v[j]));
        float ct  = tanhf(xc.v[j] + rc.v[j]);
        float cm_ = (1.0f - i_g * t1) * c0v.v[j] + i_g * ct * t1c;
        float cm  = (1.0f - i_g) * c0v.v[j] + i_g * ct * t2;
        float o   = sigf(xo.v[j] + ro.v[j] + tb * ko.v[j]);
        hv[j]  = tanhf(cm_) * o;
        cmv[j] = cm;
    }

    float* hout = out + (size_t)b * UU + u;
    float* cout = out + (size_t)BB * UU + (size_t)b * UU + u;
    *(float4*)hout = make_float4(hv[0], hv[1], hv[2], hv[3]);
    *(float4*)cout = make_float4(cmv[0], cmv[1], cmv[2], cmv[3]);
}

// ---------------- launch ----------------
extern "C" void kernel_launch(void* const* d_in, const int* in_sizes, int n_in,
                              void* d_out, int out_size) {
    const float* x     = (const float*)d_in[0];
    const float* t     = (const float*)d_in[1];
    const float* h0    = (const float*)d_in[2];
    const float* c0    = (const float*)d_in[3];
    const float* kern  = (const float*)d_in[4];
    const float* rkern = (const float*)d_in[5];
    const float* ktime = (const float*)d_in[6];
    float* out = (float*)d_out;

    __half *xh, *xl, *hh, *hl, *wh, *rh;
    cudaGetSymbolAddress((void**)&xh, g_xh);
    cudaGetSymbolAddress((void**)&xl, g_xl);
    cudaGetSymbolAddress((void**)&hh, g_hh);
    cudaGetSymbolAddress((void**)&hl, g_hl);
    cudaGetSymbolAddress((void**)&wh, g_wh);
    cudaGetSymbolAddress((void**)&rh, g_rh);

    cudaFuncSetAttribute(hmma_both,
                         cudaFuncAttributeMaxDynamicSharedMemorySize, SMEM_TOTAL);

    split_all<<<NV3 / 256, 256>>>(x, h0, kern, rkern, xh, xl, hh, hl, wh, rh);

    hmma_both<<<G1_TILES + G2_TILES, 256, SMEM_TOTAL>>>(xh, xl, wh, hh, hl, rh);

    eltwise<<<(BB * UU / 4) / 256, 256>>>(t, c0, ktime, out);
}